// round 14
// baseline (speedup 1.0000x reference)
#include <cuda_runtime.h>
#include <cuda_bf16.h>

#define MAX_NODES 65536
__device__ float g_uscore[MAX_NODES];   // bias folded in
__device__ float g_iscore[MAX_NODES];

// ---------------------------------------------------------------------------
// Node streaming: 4 rows per warp (4 independent float4 streams per lane).
// After the 4 interleaved butterfly reductions, every lane holds all four
// sums, so lane 0 writes all 4 results (NO conditional shuffles — a partial-
// warp full-mask shuffle deadlocks sm_103a; that was the R12 hang).
// ---------------------------------------------------------------------------
template <bool ADD_BIAS>
__device__ __forceinline__ void stream_rows4(const float* __restrict__ feats,
                                             const float4 w, const float bias,
                                             float* __restrict__ table,
                                             int N, int warp_id, int nwarps, int lane)
{
    const int ntask = (N + 3) >> 2;
    for (int t = warp_id; t < ntask; t += nwarps) {
        const int r0 = 4 * t;
        const float4* base = reinterpret_cast<const float4*>(feats) + (size_t)r0 * 32;

        float s0, s1, s2, s3;
        if (r0 + 3 < N) {
            const float4 v0 = base[lane];
            const float4 v1 = base[32 + lane];
            const float4 v2 = base[64 + lane];
            const float4 v3 = base[96 + lane];
            s0 = v0.x * w.x + v0.y * w.y + v0.z * w.z + v0.w * w.w;
            s1 = v1.x * w.x + v1.y * w.y + v1.z * w.z + v1.w * w.w;
            s2 = v2.x * w.x + v2.y * w.y + v2.z * w.z + v2.w * w.w;
            s3 = v3.x * w.x + v3.y * w.y + v3.z * w.z + v3.w * w.w;
        } else {
            s0 = s1 = s2 = s3 = 0.0f;
            if (r0 + 0 < N) { const float4 v = base[     lane]; s0 = v.x*w.x + v.y*w.y + v.z*w.z + v.w*w.w; }
            if (r0 + 1 < N) { const float4 v = base[32 + lane]; s1 = v.x*w.x + v.y*w.y + v.z*w.z + v.w*w.w; }
            if (r0 + 2 < N) { const float4 v = base[64 + lane]; s2 = v.x*w.x + v.y*w.y + v.z*w.z + v.w*w.w; }
            if (r0 + 3 < N) { const float4 v = base[96 + lane]; s3 = v.x*w.x + v.y*w.y + v.z*w.z + v.w*w.w; }
        }

        // 4 interleaved full-warp butterfly reductions (all lanes participate).
        #pragma unroll
        for (int o = 16; o > 0; o >>= 1) {
            s0 += __shfl_xor_sync(0xffffffffu, s0, o);
            s1 += __shfl_xor_sync(0xffffffffu, s1, o);
            s2 += __shfl_xor_sync(0xffffffffu, s2, o);
            s3 += __shfl_xor_sync(0xffffffffu, s3, o);
        }

        if (lane == 0) {
            if (ADD_BIAS) { s0 += bias; s1 += bias; s2 += bias; s3 += bias; }
            table[r0] = s0;
            if (r0 + 1 < N) table[r0 + 1] = s1;
            if (r0 + 2 < N) table[r0 + 2] = s2;
            if (r0 + 3 < N) table[r0 + 3] = s3;
        }
    }
}

__global__ void node_u_kernel(const float* __restrict__ feats,
                              const float* __restrict__ W,
                              const float* __restrict__ b, int N)
{
    const int warp = blockIdx.x * (blockDim.x >> 5) + (threadIdx.x >> 5);
    const int lane = threadIdx.x & 31;
    const int nwarps = gridDim.x * (blockDim.x >> 5);
    const float4 w = reinterpret_cast<const float4*>(W)[lane];          // W[0:128]
    stream_rows4<true>(feats, w, b[0], g_uscore, N, warp, nwarps, lane);
}

__global__ void node_i_kernel(const float* __restrict__ feats,
                              const float* __restrict__ W, int N)
{
    const int warp = blockIdx.x * (blockDim.x >> 5) + (threadIdx.x >> 5);
    const int lane = threadIdx.x & 31;
    const int nwarps = gridDim.x * (blockDim.x >> 5);
    const float4 w = (reinterpret_cast<const float4*>(W) + 32)[lane];   // W[128:256]
    stream_rows4<false>(feats, w, 0.0f, g_iscore, N, warp, nwarps, lane);
}

// ---------------------------------------------------------------------------
// Edge pass 1: out[e] = u[src[e]]  (grid-stride, co-resident with node_i)
// ---------------------------------------------------------------------------
__global__ void edge_u_kernel(const int2* __restrict__ src2,
                              const int* __restrict__ src_idx,
                              float* __restrict__ out, int E2, int E)
{
    const int tid = blockIdx.x * blockDim.x + threadIdx.x;
    const int nt  = gridDim.x * blockDim.x;
    float2* o2 = reinterpret_cast<float2*>(out);
    for (int i = tid; i < E2; i += nt) {
        const int2 s = src2[i];
        float2 r;
        r.x = g_uscore[s.x];
        r.y = g_uscore[s.y];
        o2[i] = r;
    }
    if (tid == 0 && (E & 1))
        out[E - 1] = g_uscore[src_idx[E - 1]];
}

// ---------------------------------------------------------------------------
// Edge pass 2: out[e] += i[dst[e]]  (one-shot; out re-read hits L2)
// ---------------------------------------------------------------------------
__global__ void edge_add_kernel(const int2* __restrict__ dst2,
                                const int* __restrict__ dst_idx,
                                float* __restrict__ out, int E2, int E)
{
    const int i = blockIdx.x * blockDim.x + threadIdx.x;
    if (i < E2) {
        const int2 d = dst2[i];
        float2* o2 = reinterpret_cast<float2*>(out);
        float2 r = o2[i];
        r.x += g_iscore[d.x];
        r.y += g_iscore[d.y];
        o2[i] = r;
    }
    if (i == 0 && (E & 1))
        out[E - 1] += g_iscore[dst_idx[E - 1]];
}

// ---------------------------------------------------------------------------
// Graph: nodeU ──┬─ edgeU(296 blk) ───┬─ edgeAdd
//                └─ nodeI(296 blk, side stream) ──┘
// Both middle kernels are half-machine grids -> co-resident overlap.
// ---------------------------------------------------------------------------
extern "C" void kernel_launch(void* const* d_in, const int* in_sizes, int n_in,
                              void* d_out, int out_size)
{
    const float* user_feats = (const float*)d_in[0];
    const float* item_feats = (const float*)d_in[1];
    const int*   src_idx    = (const int*)d_in[2];
    const int*   dst_idx    = (const int*)d_in[3];
    const float* W          = (const float*)d_in[4];
    const float* b          = (const float*)d_in[5];
    float*       out        = (float*)d_out;

    const int Nu = in_sizes[0] / 128;
    const int Ni = in_sizes[1] / 128;
    const int E  = in_sizes[2];
    const int E2 = E / 2;

    static cudaStream_t s_side = nullptr;
    static cudaEvent_t  e_fork = nullptr, e_join = nullptr;
    if (s_side == nullptr) {
        cudaStreamCreateWithFlags(&s_side, cudaStreamNonBlocking);
        cudaEventCreateWithFlags(&e_fork, cudaEventDisableTiming);
        cudaEventCreateWithFlags(&e_join, cudaEventDisableTiming);
    }

    // 1) nodeU: full machine, 4 rows/warp, 8 warps/block -> 32 rows/block.
    {
        const int blocks = (Nu + 31) / 32;
        node_u_kernel<<<blocks, 256, 0, 0>>>(user_feats, W, b, Nu);
    }

    if (s_side && e_fork && e_join) {
        // 2) fork: nodeI on side stream, half-machine grid (co-resident).
        cudaEventRecord(e_fork, 0);
        cudaStreamWaitEvent(s_side, e_fork, 0);
        node_i_kernel<<<296, 256, 0, s_side>>>(item_feats, W, Ni);
        cudaEventRecord(e_join, s_side);

        // 3) edgeU on main stream, half-machine grid (overlaps nodeI).
        edge_u_kernel<<<296, 256, 0, 0>>>((const int2*)src_idx, src_idx, out, E2, E);

        // 4) join, then edgeAdd one-shot.
        cudaStreamWaitEvent(0, e_join, 0);
        const int ablocks = (E2 + 255) / 256;
        edge_add_kernel<<<ablocks, 256, 0, 0>>>((const int2*)dst_idx, dst_idx, out, E2, E);
    } else {
        node_i_kernel<<<296, 256, 0, 0>>>(item_feats, W, Ni);
        edge_u_kernel<<<296, 256, 0, 0>>>((const int2*)src_idx, src_idx, out, E2, E);
        const int ablocks = (E2 + 255) / 256;
        edge_add_kernel<<<ablocks, 256, 0, 0>>>((const int2*)dst_idx, dst_idx, out, E2, E);
    }
}

// round 15
// speedup vs baseline: 1.0562x; 1.0562x over previous
#include <cuda_runtime.h>
#include <cuda_bf16.h>

#define MAX_NODES 65536
__device__ float g_uscore[MAX_NODES];   // bias folded in
__device__ float g_iscore[MAX_NODES];

// ---------------------------------------------------------------------------
// Node streaming: 4 rows per warp (4 independent float4 streams per lane).
// After the 4 interleaved butterfly reductions, every lane holds all four
// sums, so lane 0 writes all 4 results (NO conditional shuffles — a partial-
// warp full-mask shuffle deadlocks sm_103a; that was the R12 hang).
// ---------------------------------------------------------------------------
template <bool ADD_BIAS>
__device__ __forceinline__ void stream_rows4(const float* __restrict__ feats,
                                             const float4 w, const float bias,
                                             float* __restrict__ table,
                                             int N, int warp_id, int nwarps, int lane)
{
    const int ntask = (N + 3) >> 2;
    for (int t = warp_id; t < ntask; t += nwarps) {
        const int r0 = 4 * t;
        const float4* base = reinterpret_cast<const float4*>(feats) + (size_t)r0 * 32;

        float s0, s1, s2, s3;
        if (r0 + 3 < N) {
            const float4 v0 = base[lane];
            const float4 v1 = base[32 + lane];
            const float4 v2 = base[64 + lane];
            const float4 v3 = base[96 + lane];
            s0 = v0.x * w.x + v0.y * w.y + v0.z * w.z + v0.w * w.w;
            s1 = v1.x * w.x + v1.y * w.y + v1.z * w.z + v1.w * w.w;
            s2 = v2.x * w.x + v2.y * w.y + v2.z * w.z + v2.w * w.w;
            s3 = v3.x * w.x + v3.y * w.y + v3.z * w.z + v3.w * w.w;
        } else {
            s0 = s1 = s2 = s3 = 0.0f;
            if (r0 + 0 < N) { const float4 v = base[     lane]; s0 = v.x*w.x + v.y*w.y + v.z*w.z + v.w*w.w; }
            if (r0 + 1 < N) { const float4 v = base[32 + lane]; s1 = v.x*w.x + v.y*w.y + v.z*w.z + v.w*w.w; }
            if (r0 + 2 < N) { const float4 v = base[64 + lane]; s2 = v.x*w.x + v.y*w.y + v.z*w.z + v.w*w.w; }
            if (r0 + 3 < N) { const float4 v = base[96 + lane]; s3 = v.x*w.x + v.y*w.y + v.z*w.z + v.w*w.w; }
        }

        // 4 interleaved full-warp butterfly reductions (all lanes participate).
        #pragma unroll
        for (int o = 16; o > 0; o >>= 1) {
            s0 += __shfl_xor_sync(0xffffffffu, s0, o);
            s1 += __shfl_xor_sync(0xffffffffu, s1, o);
            s2 += __shfl_xor_sync(0xffffffffu, s2, o);
            s3 += __shfl_xor_sync(0xffffffffu, s3, o);
        }

        if (lane == 0) {
            if (ADD_BIAS) { s0 += bias; s1 += bias; s2 += bias; s3 += bias; }
            table[r0] = s0;
            if (r0 + 1 < N) table[r0 + 1] = s1;
            if (r0 + 2 < N) table[r0 + 2] = s2;
            if (r0 + 3 < N) table[r0 + 3] = s3;
        }
    }
}

__global__ void node_u_kernel(const float* __restrict__ feats,
                              const float* __restrict__ W,
                              const float* __restrict__ b, int N)
{
    const int warp = blockIdx.x * (blockDim.x >> 5) + (threadIdx.x >> 5);
    const int lane = threadIdx.x & 31;
    const int nwarps = gridDim.x * (blockDim.x >> 5);
    const float4 w = reinterpret_cast<const float4*>(W)[lane];          // W[0:128]
    stream_rows4<true>(feats, w, b[0], g_uscore, N, warp, nwarps, lane);
}

__global__ void node_i_kernel(const float* __restrict__ feats,
                              const float* __restrict__ W, int N)
{
    const int warp = blockIdx.x * (blockDim.x >> 5) + (threadIdx.x >> 5);
    const int lane = threadIdx.x & 31;
    const int nwarps = gridDim.x * (blockDim.x >> 5);
    const float4 w = (reinterpret_cast<const float4*>(W) + 32)[lane];   // W[128:256]
    stream_rows4<false>(feats, w, 0.0f, g_iscore, N, warp, nwarps, lane);
}

// ---------------------------------------------------------------------------
// Edge pass 1: out[e] = u[src[e]]  (grid-stride, co-resident with node_i)
// ---------------------------------------------------------------------------
__global__ void edge_u_kernel(const int2* __restrict__ src2,
                              const int* __restrict__ src_idx,
                              float* __restrict__ out, int E2, int E)
{
    const int tid = blockIdx.x * blockDim.x + threadIdx.x;
    const int nt  = gridDim.x * blockDim.x;
    float2* o2 = reinterpret_cast<float2*>(out);
    for (int i = tid; i < E2; i += nt) {
        const int2 s = src2[i];
        float2 r;
        r.x = g_uscore[s.x];
        r.y = g_uscore[s.y];
        o2[i] = r;
    }
    if (tid == 0 && (E & 1))
        out[E - 1] = g_uscore[src_idx[E - 1]];
}

// ---------------------------------------------------------------------------
// Edge pass 2: out[e] += i[dst[e]]  (one-shot; out re-read hits L2)
// ---------------------------------------------------------------------------
__global__ void edge_add_kernel(const int2* __restrict__ dst2,
                                const int* __restrict__ dst_idx,
                                float* __restrict__ out, int E2, int E)
{
    const int i = blockIdx.x * blockDim.x + threadIdx.x;
    if (i < E2) {
        const int2 d = dst2[i];
        float2* o2 = reinterpret_cast<float2*>(out);
        float2 r = o2[i];
        r.x += g_iscore[d.x];
        r.y += g_iscore[d.y];
        o2[i] = r;
    }
    if (i == 0 && (E & 1))
        out[E - 1] += g_iscore[dst_idx[E - 1]];
}

// ---------------------------------------------------------------------------
// Graph: nodeU ──┬─ edgeU(296 blk) ───┬─ edgeAdd
//                └─ nodeI(296 blk, side stream) ──┘
// Both middle kernels are half-machine grids -> co-resident overlap.
// ---------------------------------------------------------------------------
extern "C" void kernel_launch(void* const* d_in, const int* in_sizes, int n_in,
                              void* d_out, int out_size)
{
    const float* user_feats = (const float*)d_in[0];
    const float* item_feats = (const float*)d_in[1];
    const int*   src_idx    = (const int*)d_in[2];
    const int*   dst_idx    = (const int*)d_in[3];
    const float* W          = (const float*)d_in[4];
    const float* b          = (const float*)d_in[5];
    float*       out        = (float*)d_out;

    const int Nu = in_sizes[0] / 128;
    const int Ni = in_sizes[1] / 128;
    const int E  = in_sizes[2];
    const int E2 = E / 2;

    static cudaStream_t s_side = nullptr;
    static cudaEvent_t  e_fork = nullptr, e_join = nullptr;
    if (s_side == nullptr) {
        cudaStreamCreateWithFlags(&s_side, cudaStreamNonBlocking);
        cudaEventCreateWithFlags(&e_fork, cudaEventDisableTiming);
        cudaEventCreateWithFlags(&e_join, cudaEventDisableTiming);
    }

    // 1) nodeU: full machine, 4 rows/warp, 8 warps/block -> 32 rows/block.
    {
        const int blocks = (Nu + 31) / 32;
        node_u_kernel<<<blocks, 256, 0, 0>>>(user_feats, W, b, Nu);
    }

    if (s_side && e_fork && e_join) {
        // 2) fork: nodeI on side stream, half-machine grid (co-resident).
        cudaEventRecord(e_fork, 0);
        cudaStreamWaitEvent(s_side, e_fork, 0);
        node_i_kernel<<<296, 256, 0, s_side>>>(item_feats, W, Ni);
        cudaEventRecord(e_join, s_side);

        // 3) edgeU on main stream, half-machine grid (overlaps nodeI).
        edge_u_kernel<<<296, 256, 0, 0>>>((const int2*)src_idx, src_idx, out, E2, E);

        // 4) join, then edgeAdd one-shot.
        cudaStreamWaitEvent(0, e_join, 0);
        const int ablocks = (E2 + 255) / 256;
        edge_add_kernel<<<ablocks, 256, 0, 0>>>((const int2*)dst_idx, dst_idx, out, E2, E);
    } else {
        node_i_kernel<<<296, 256, 0, 0>>>(item_feats, W, Ni);
        edge_u_kernel<<<296, 256, 0, 0>>>((const int2*)src_idx, src_idx, out, E2, E);
        const int ablocks = (E2 + 255) / 256;
        edge_add_kernel<<<ablocks, 256, 0, 0>>>((const int2*)dst_idx, dst_idx, out, E2, E);
    }
}